// round 2
// baseline (speedup 1.0000x reference)
#include <cuda_runtime.h>
#include <cuda_bf16.h>
#include <cstdint>
#include <cstddef>
#include <math.h>

namespace g {
constexpr int B    = 32;
constexpr int A    = 4;
constexpr int NPER = 2048;
constexpr int N    = 8192;      // A*NPER
constexpr int DIN  = 1024;
constexpr int OUTD = 11;
constexpr float THRESH = 0.05f;
constexpr float SELFM  = 0.8f;
constexpr float CROSSM = 0.1f;
}

// ---------------- device scratch (no allocations allowed) ----------------
__device__ float g_gate[g::A];
__device__ int   g_perm[g::N];
__device__ float g_Ueff[(size_t)g::A * g::N * g::B];  // [o][c][b], 4 MB
__device__ float g_Xt[(size_t)g::DIN * g::B];         // [k][b]
__device__ float g_part[2ul * g::N * g::B];           // [kh][j][b], 2 MB
__device__ float g_Z[(size_t)g::B * g::N];            // Z_flat[b][q], 1 MB

// =========================================================================
// 1) decode area_idx (handles int32 or int64 payload) -> g_perm
// =========================================================================
__global__ void k_decode(const void* area_idx_raw) {
    const unsigned* w32 = (const unsigned*)area_idx_raw;
    int t = threadIdx.x;  // 1024 threads
    unsigned acc = 0;
    // If data is int64 (values < 2^31), every odd 32-bit word is 0.
    for (int i = t; i < g::N; i += 1024) acc |= w32[2 * i + 1];
    for (int o = 16; o; o >>= 1) acc |= __shfl_xor_sync(0xFFFFFFFFu, acc, o);
    __shared__ unsigned red[32];
    __shared__ int is64_s;
    if ((t & 31) == 0) red[t >> 5] = acc;
    __syncthreads();
    if (t < 32) {
        unsigned v = red[t];
        for (int o = 16; o; o >>= 1) v |= __shfl_xor_sync(0xFFFFFFFFu, v, o);
        if (t == 0) is64_s = (v == 0u) ? 1 : 0;
    }
    __syncthreads();
    bool is64 = (is64_s != 0);
    const long long* p64 = (const long long*)area_idx_raw;
    const int*       p32 = (const int*)area_idx_raw;
    for (int i = t; i < g::N; i += 1024)
        g_perm[i] = is64 ? (int)p64[i] : p32[i];
}

// =========================================================================
// 2) gate[a] = (mean_{b,m} |Z0[b,a,m]| > THRESH) ? 1 : 0
// =========================================================================
__global__ void k_gate(const float* __restrict__ Z0) {
    int a = blockIdx.x;
    int t = threadIdx.x;  // 256
    float s = 0.f;
    const int TOT = g::B * g::NPER;
    for (int i = t; i < TOT; i += 256) {
        int b = i >> 11, m = i & (g::NPER - 1);
        s += fabsf(Z0[((size_t)b * g::A + a) * g::NPER + m]);
    }
    for (int o = 16; o; o >>= 1) s += __shfl_xor_sync(0xFFFFFFFFu, s, o);
    __shared__ float red[8];
    if ((t & 31) == 0) red[t >> 5] = s;
    __syncthreads();
    if (t == 0) {
        float tot = 0.f;
        for (int i = 0; i < 8; i++) tot += red[i];
        g_gate[a] = (tot / (float)TOT > g::THRESH) ? 1.f : 0.f;
    }
}

// =========================================================================
// 3) build Ueff[o][c][b] = scale[o, area(k)] * gate[area(k)] * Z0[b,k]
//    where c = perm[k]; also Xt[k][b] = x[b][k]
// =========================================================================
__global__ void k_build(const float* __restrict__ Z0, const float* __restrict__ x) {
    int b = blockIdx.y;
    int j = blockIdx.x * 256 + threadIdx.x;      // position in perm order
    int c = g_perm[j];
    int a = j >> 11;
    float zg = Z0[((size_t)b * g::A + a) * g::NPER + (j & (g::NPER - 1))] * g_gate[a];
#pragma unroll
    for (int o = 0; o < g::A; o++) {
        float sc = (o == a) ? g::SELFM : g::CROSSM;
        g_Ueff[(((size_t)o * g::N + c) << 5) + b] = sc * zg;
    }
    if (j < g::DIN) g_Xt[((size_t)j << 5) + b] = x[(size_t)b * g::DIN + j];
}

// =========================================================================
// 4) main GEMM: part[kh][j][b] = sum over this K-half of
//    synapses_w[perm[j], c]*Ueff[o][c][b]  +  receptors_w[perm[j], k]*Xt[k][b]
//    64 rows/CTA, 128 threads, 4x4 thread tile, K chunk 64, reg prefetch.
// =========================================================================
__global__ void __launch_bounds__(128) k_main(const float* __restrict__ Wsyn,
                                              const float* __restrict__ Wrec) {
    __shared__ float sW[64][65];     // [kk][row]
    __shared__ float sU[64 * 32];    // [kk][b]
    __shared__ int   srow[64];

    const int t  = threadIdx.x;
    const int j0 = blockIdx.x * 64;          // 128 row-groups
    const int kh = blockIdx.y;               // K split half
    const int o  = j0 >> 11;                 // output area (uniform per CTA)

    if (t < 64) srow[t] = g_perm[j0 + t];
    __syncthreads();

    const float* Uo = g_Ueff + (size_t)o * g::N * g::B;

    const int rr  = t >> 1;           // staged row 0..63
    const int kh2 = (t & 1) * 32;     // staged k-half within chunk
    const int r0  = (t & 15) * 4;     // compute row base
    const int b0  = (t >> 4) * 4;     // compute batch base

    float acc[4][4];
#pragma unroll
    for (int i = 0; i < 4; i++)
#pragma unroll
        for (int j = 0; j < 4; j++) acc[i][j] = 0.f;

    constexpr int NCH0 = 4096 / 64;   // 64 synapse chunks per half
    constexpr int NCH1 = 512 / 64;    // 8 receptor chunks per half
    constexpr int NCH  = NCH0 + NCH1; // 72

    float4 wreg[8], ureg[4];

    auto prefetch = [&](int q) {
        const float* Wm; const float* Um; int ld, colbase;
        if (q < NCH0) { Wm = Wsyn; Um = Uo;   ld = g::N;   colbase = kh * 4096 + q * 64; }
        else          { Wm = Wrec; Um = g_Xt; ld = g::DIN; colbase = kh * 512 + (q - NCH0) * 64; }
        const float4* wsrc = (const float4*)(Wm + (size_t)srow[rr] * ld + colbase + kh2);
#pragma unroll
        for (int i = 0; i < 8; i++) wreg[i] = wsrc[i];
        const float4* usrc = (const float4*)(Um + (size_t)colbase * g::B);
#pragma unroll
        for (int i = 0; i < 4; i++) ureg[i] = usrc[t + i * 128];
    };

    prefetch(0);

    for (int q = 0; q < NCH; q++) {
        __syncthreads();   // previous tile fully consumed
#pragma unroll
        for (int i = 0; i < 8; i++) {
            int kk = kh2 + i * 4;
            sW[kk + 0][rr] = wreg[i].x;
            sW[kk + 1][rr] = wreg[i].y;
            sW[kk + 2][rr] = wreg[i].z;
            sW[kk + 3][rr] = wreg[i].w;
        }
#pragma unroll
        for (int i = 0; i < 4; i++) ((float4*)sU)[t + i * 128] = ureg[i];
        __syncthreads();

        if (q + 1 < NCH) prefetch(q + 1);   // overlap LDG with compute

#pragma unroll 4
        for (int kk = 0; kk < 64; kk++) {
            float w0 = sW[kk][r0 + 0], w1 = sW[kk][r0 + 1];
            float w2 = sW[kk][r0 + 2], w3 = sW[kk][r0 + 3];
            const float* u = sU + kk * 32 + b0;
            float u0 = u[0], u1 = u[1], u2 = u[2], u3 = u[3];
            acc[0][0] += w0 * u0; acc[0][1] += w0 * u1; acc[0][2] += w0 * u2; acc[0][3] += w0 * u3;
            acc[1][0] += w1 * u0; acc[1][1] += w1 * u1; acc[1][2] += w1 * u2; acc[1][3] += w1 * u3;
            acc[2][0] += w2 * u0; acc[2][1] += w2 * u1; acc[2][2] += w2 * u2; acc[2][3] += w2 * u3;
            acc[3][0] += w3 * u0; acc[3][1] += w3 * u1; acc[3][2] += w3 * u2; acc[3][3] += w3 * u3;
        }
    }

    float* out = g_part + (size_t)kh * g::N * g::B;
#pragma unroll
    for (int i = 0; i < 4; i++) {
        int j = j0 + r0 + i;
#pragma unroll
        for (int jb = 0; jb < 4; jb++)
            out[((size_t)j << 5) + b0 + jb] = acc[i][jb];
    }
}

// =========================================================================
// 5) combine halves + bias + tanh + scatter to Z_flat
// =========================================================================
__global__ void k_final(const float* __restrict__ bsyn, const float* __restrict__ brec) {
    int idx = blockIdx.x * 256 + threadIdx.x;   // over j*32+b
    int j = idx >> 5, b = idx & 31;
    int rp = g_perm[j];
    int o = j >> 11;
    float v = g_part[idx] + g_part[(size_t)g::N * g::B + idx]
            + g_gate[o] * bsyn[rp] + brec[rp];
    g_Z[(size_t)b * g::N + rp] = tanhf(v);
}

// =========================================================================
// 6) output lobe: raw[b][t] = Z_flat[b] . Wout[t] + bout[t]
// =========================================================================
__global__ void k_out(const float* __restrict__ Wout, const float* __restrict__ bout,
                      float* __restrict__ out) {
    int tt = blockIdx.x;   // 0..10
    int b  = blockIdx.y;   // 0..31
    int t  = threadIdx.x;  // 256
    const float* wrow = Wout + (size_t)tt * g::N;
    const float* zrow = g_Z + (size_t)b * g::N;
    float s = 0.f;
    for (int q = t; q < g::N; q += 256) s += wrow[q] * zrow[q];
    for (int o = 16; o; o >>= 1) s += __shfl_xor_sync(0xFFFFFFFFu, s, o);
    __shared__ float red[8];
    if ((t & 31) == 0) red[t >> 5] = s;
    __syncthreads();
    if (t == 0) {
        float tot = 0.f;
        for (int i = 0; i < 8; i++) tot += red[i];
        tot += bout[tt];
        if (tt < 10) out[(size_t)b * 10 + tt] = tot;
        else         out[320 + b] = 1.f / (1.f + expf(-tot));
    }
}

// =========================================================================
extern "C" void kernel_launch(void* const* d_in, const int* in_sizes, int n_in,
                              void* d_out, int out_size) {
    const float* x     = (const float*)d_in[0];
    const float* Z0    = (const float*)d_in[1];
    const float* Wrec  = (const float*)d_in[2];
    const float* brec  = (const float*)d_in[3];
    const float* Wsyn  = (const float*)d_in[4];
    const float* bsyn  = (const float*)d_in[5];
    const float* Wout  = (const float*)d_in[6];
    const float* bout  = (const float*)d_in[7];
    const void*  aidx  = d_in[8];
    float* out = (float*)d_out;

    k_decode<<<1, 1024>>>(aidx);
    k_gate<<<g::A, 256>>>(Z0);
    k_build<<<dim3(g::N / 256, g::B), 256>>>(Z0, x);
    k_main<<<dim3(g::N / 64, 2), 128>>>(Wsyn, Wrec);
    k_final<<<(g::N * g::B) / 256, 256>>>(bsyn, brec);
    k_out<<<dim3(g::OUTD, g::B), 256>>>(Wout, bout, out);
}

// round 4
// speedup vs baseline: 3.1331x; 3.1331x over previous
#include <cuda_runtime.h>
#include <cuda_bf16.h>
#include <cstdint>
#include <cstddef>
#include <math.h>

namespace g {
constexpr int B = 32, A = 4, NPER = 2048, N = 8192, DIN = 1024, OUTD = 11;
constexpr int KTOT   = N + DIN;              // 9216
constexpr int KSPLIT = 4;
constexpr int KPART  = KTOT / KSPLIT;        // 2304
constexpr int KC     = 32;                   // k per chunk
constexpr int MT     = 128;                  // rows per CTA
constexpr int NCH    = KPART / KC;           // 72
constexpr int STAGES = 4;
constexpr float THRESH = 0.05f;

// smem strides (floats) chosen for conflict-free mma fragment loads
constexpr int ASTR = 36;                     // A row stride: bank (4*row + k) distinct
constexpr int BSTR = 40;                     // B row stride: bank (8*k + n) distinct
constexpr int SA_F = MT * ASTR;              // 4608 floats  (18432 B)
constexpr int SB_F = KC * BSTR;              // 1280 floats  (5120 B)
constexpr int STAGE_F = SA_F + SB_F;         // 5888 floats  (23552 B)
constexpr int SM_TOTAL = STAGES * STAGE_F * 4;  // 94208 B
}

// ------------------ device scratch ------------------
__device__ float g_gate[g::A];
__device__ int   g_perm[g::N];                              // perm order -> natural col
__device__ float g_Ueff[(size_t)g::A * g::N * g::B];        // [o][c][b], scale-folded, 4 MB
__device__ float g_Xt[(size_t)g::DIN * g::B];               // [k][b]
__device__ float g_part[(size_t)g::KSPLIT * g::N * g::B];   // [kh][j][b], 4 MB
__device__ float g_Z[(size_t)g::B * g::N];                  // Z_flat[b][q]

// ------------------ helpers ------------------
__device__ __forceinline__ uint32_t smem_u32(const void* p) {
    uint32_t a;
    asm("{ .reg .u64 t; cvta.to.shared.u64 t, %1; cvt.u32.u64 %0, t; }" : "=r"(a) : "l"(p));
    return a;
}
__device__ __forceinline__ void cp16(uint32_t dst, const void* src) {
    asm volatile("cp.async.cg.shared.global [%0], [%1], 16;" :: "r"(dst), "l"(src) : "memory");
}
#define CP_COMMIT() asm volatile("cp.async.commit_group;" ::: "memory")
#define CP_WAIT2()  asm volatile("cp.async.wait_group 2;" ::: "memory")

__device__ __forceinline__ float rna_tf32(float v) {
    float r;
    asm("cvt.rna.tf32.f32 %0, %1;" : "=f"(r) : "f"(v));
    return r;
}
__device__ __forceinline__ uint32_t cvt_tf32_bits(float v) {
    uint32_t r;
    asm("cvt.rna.tf32.f32 %0, %1;" : "=r"(r) : "f"(v));
    return r;
}
__device__ __forceinline__ void mma_tf32(float& d0, float& d1, float& d2, float& d3,
                                         uint32_t a0, uint32_t a1, uint32_t a2, uint32_t a3,
                                         uint32_t b0, uint32_t b1) {
    asm volatile(
        "mma.sync.aligned.m16n8k8.row.col.f32.tf32.tf32.f32 "
        "{%0,%1,%2,%3}, {%4,%5,%6,%7}, {%8,%9}, {%0,%1,%2,%3};"
        : "+f"(d0), "+f"(d1), "+f"(d2), "+f"(d3)
        : "r"(a0), "r"(a1), "r"(a2), "r"(a3), "r"(b0), "r"(b1));
}

// =========================================================================
// 1) decode area_idx (int32 or int64) -> g_perm
// =========================================================================
__global__ void k_decode(const void* area_idx_raw) {
    const unsigned* w32 = (const unsigned*)area_idx_raw;
    int t = threadIdx.x;  // 1024
    unsigned acc = 0;
    for (int i = t; i < g::N; i += 1024) acc |= w32[2 * i + 1];
    for (int o = 16; o; o >>= 1) acc |= __shfl_xor_sync(0xFFFFFFFFu, acc, o);
    __shared__ unsigned red[32];
    __shared__ int is64_s;
    if ((t & 31) == 0) red[t >> 5] = acc;
    __syncthreads();
    if (t < 32) {
        unsigned v = red[t];
        for (int o = 16; o; o >>= 1) v |= __shfl_xor_sync(0xFFFFFFFFu, v, o);
        if (t == 0) is64_s = (v == 0u) ? 1 : 0;
    }
    __syncthreads();
    bool is64 = (is64_s != 0);
    const long long* p64 = (const long long*)area_idx_raw;
    const int*       p32 = (const int*)area_idx_raw;
    for (int i = t; i < g::N; i += 1024)
        g_perm[i] = is64 ? (int)p64[i] : p32[i];
}

// =========================================================================
// 2) gate
// =========================================================================
__global__ void k_gate(const float* __restrict__ Z0) {
    int a = blockIdx.x, t = threadIdx.x;
    float s = 0.f;
    const int TOT = g::B * g::NPER;
    for (int i = t; i < TOT; i += 256) {
        int b = i >> 11, m = i & (g::NPER - 1);
        s += fabsf(Z0[((size_t)b * g::A + a) * g::NPER + m]);
    }
    for (int o = 16; o; o >>= 1) s += __shfl_xor_sync(0xFFFFFFFFu, s, o);
    __shared__ float red[8];
    if ((t & 31) == 0) red[t >> 5] = s;
    __syncthreads();
    if (t == 0) {
        float tot = 0.f;
        for (int i = 0; i < 8; i++) tot += red[i];
        g_gate[a] = (tot / (float)TOT > g::THRESH) ? 1.f : 0.f;
    }
}

// =========================================================================
// 3) Ueff[o][c][b] = rna_tf32(scale[o,area(c)] * gate * Z0[b, c-in-perm]);
//    Xt[k][b] = rna_tf32(x[b][k])
// =========================================================================
__global__ void k_build(const float* __restrict__ Z0, const float* __restrict__ x) {
    int b = blockIdx.y;
    int j = blockIdx.x * 256 + threadIdx.x;  // perm position
    int c = g_perm[j];
    int a = j >> 11;
    float zg = Z0[((size_t)b * g::A + a) * g::NPER + (j & (g::NPER - 1))] * g_gate[a];
#pragma unroll
    for (int o = 0; o < g::A; o++) {
        float sc = (o == a) ? 0.8f : 0.1f;
        g_Ueff[(((size_t)o * g::N + c) << 5) + b] = rna_tf32(sc * zg);
    }
    if (j < g::DIN) g_Xt[((size_t)j << 5) + b] = rna_tf32(x[(size_t)b * g::DIN + j]);
}

// =========================================================================
// 4) main GEMM via mma.sync tf32. grid (64, 4), 256 threads (8 warps).
//    part[kh][j][b] = sum_k W[perm[j],k] * B[k][b] over this K quarter.
// =========================================================================
__global__ void __launch_bounds__(256) k_main(const float* __restrict__ Wsyn,
                                              const float* __restrict__ Wrec) {
    extern __shared__ float smem[];
    __shared__ int srow[g::MT];
    const uint32_t su = smem_u32(smem);

    const int tid = threadIdx.x, wid = tid >> 5, lane = tid & 31;
    const int gq = lane >> 2, tq = lane & 3;     // groupID, threadID_in_group
    const int j0 = blockIdx.x * g::MT;
    const int o  = j0 >> 11;                     // area (uniform per CTA)
    const int kh = blockIdx.y;
    const int kbase = kh * g::KPART;

    if (tid < g::MT) srow[tid] = g_perm[j0 + tid];
    __syncthreads();

    const float* Uo = g_Ueff + (size_t)o * g::N * g::B;

    auto issue = [&](int q) {
        const int s = q & (g::STAGES - 1);
        const int k0 = kbase + q * g::KC;
        const float* wb; int ld, col;
        if (k0 < g::N) { wb = Wsyn; ld = g::N;   col = k0; }
        else           { wb = Wrec; ld = g::DIN; col = k0 - g::N; }
        const uint32_t sbase = su + s * (g::STAGE_F * 4);
        // A: 128 rows x 32 k -> 1024 granules of 16B
#pragma unroll
        for (int i = 0; i < 4; i++) {
            int ga = tid + i * 256;
            int row = ga >> 3, kg = ga & 7;
            const float* src = wb + (size_t)srow[row] * ld + col + kg * 4;
            cp16(sbase + row * (g::ASTR * 4) + kg * 16, src);
        }
        // B: 32 k x 32 b -> 256 granules
        {
            int krow = tid >> 3, ng = tid & 7;
            const float* src = (k0 < g::N)
                ? Uo + (((size_t)(k0 + krow)) << 5) + ng * 4
                : g_Xt + (((size_t)(k0 - g::N + krow)) << 5) + ng * 4;
            cp16(sbase + g::SA_F * 4 + krow * (g::BSTR * 4) + ng * 16, src);
        }
    };

    float acc[4][4];
#pragma unroll
    for (int i = 0; i < 4; i++)
#pragma unroll
        for (int jn = 0; jn < 4; jn++) acc[i][jn] = 0.f;

    for (int q = 0; q < g::STAGES - 1; q++) { issue(q); CP_COMMIT(); }

    const int arow = wid * 16 + gq;

    for (int q = 0; q < g::NCH; q++) {
        CP_WAIT2();
        __syncthreads();
        if (q + g::STAGES - 1 < g::NCH) issue(q + g::STAGES - 1);
        CP_COMMIT();

        const int s = q & (g::STAGES - 1);
        const float* As = smem + s * g::STAGE_F;
        const float* Bs = As + g::SA_F;
#pragma unroll
        for (int ks = 0; ks < 4; ks++) {
            const int kk = ks * 8;
            uint32_t a0 = cvt_tf32_bits(As[arow * g::ASTR + kk + tq]);
            uint32_t a1 = cvt_tf32_bits(As[(arow + 8) * g::ASTR + kk + tq]);
            uint32_t a2 = cvt_tf32_bits(As[arow * g::ASTR + kk + tq + 4]);
            uint32_t a3 = cvt_tf32_bits(As[(arow + 8) * g::ASTR + kk + tq + 4]);
#pragma unroll
            for (int nt = 0; nt < 4; nt++) {
                uint32_t b0 = __float_as_uint(Bs[(kk + tq) * g::BSTR + nt * 8 + gq]);
                uint32_t b1 = __float_as_uint(Bs[(kk + tq + 4) * g::BSTR + nt * 8 + gq]);
                mma_tf32(acc[nt][0], acc[nt][1], acc[nt][2], acc[nt][3],
                         a0, a1, a2, a3, b0, b1);
            }
        }
    }

    // epilogue: D fragment (16x8 per ntile): c0 (gq, 2tq), c1 (gq, 2tq+1),
    // c2 (gq+8, 2tq), c3 (gq+8, 2tq+1)
    float* dst = g_part + (size_t)kh * ((size_t)g::N * g::B);
    const int jr = j0 + wid * 16 + gq;
#pragma unroll
    for (int nt = 0; nt < 4; nt++) {
        int bcol = nt * 8 + 2 * tq;
        dst[(size_t)jr * 32 + bcol]           = acc[nt][0];
        dst[(size_t)jr * 32 + bcol + 1]       = acc[nt][1];
        dst[(size_t)(jr + 8) * 32 + bcol]     = acc[nt][2];
        dst[(size_t)(jr + 8) * 32 + bcol + 1] = acc[nt][3];
    }
}

// =========================================================================
// 5) combine K-split partials + bias + tanh + scatter
// =========================================================================
__global__ void k_final(const float* __restrict__ bsyn, const float* __restrict__ brec) {
    size_t idx = (size_t)blockIdx.x * 256 + threadIdx.x;  // j*32+b
    int j = (int)(idx >> 5), b = (int)(idx & 31);
    int rp = g_perm[j];
    int o = j >> 11;
    constexpr size_t S = (size_t)g::N * g::B;
    float v = g_part[idx] + g_part[idx + S] + g_part[idx + 2 * S] + g_part[idx + 3 * S]
            + g_gate[o] * bsyn[rp] + brec[rp];
    g_Z[(size_t)b * g::N + rp] = tanhf(v);
}

// =========================================================================
// 6) output lobe
// =========================================================================
__global__ void k_out(const float* __restrict__ Wout, const float* __restrict__ bout,
                      float* __restrict__ out) {
    int tt = blockIdx.x, b = blockIdx.y, t = threadIdx.x;
    const float* wrow = Wout + (size_t)tt * g::N;
    const float* zrow = g_Z + (size_t)b * g::N;
    float s = 0.f;
    for (int q = t; q < g::N; q += 256) s += wrow[q] * zrow[q];
    for (int o = 16; o; o >>= 1) s += __shfl_xor_sync(0xFFFFFFFFu, s, o);
    __shared__ float red[8];
    if ((t & 31) == 0) red[t >> 5] = s;
    __syncthreads();
    if (t == 0) {
        float tot = 0.f;
        for (int i = 0; i < 8; i++) tot += red[i];
        tot += bout[tt];
        if (tt < 10) out[(size_t)b * 10 + tt] = tot;
        else         out[320 + b] = 1.f / (1.f + expf(-tot));
    }
}

// =========================================================================
extern "C" void kernel_launch(void* const* d_in, const int* in_sizes, int n_in,
                              void* d_out, int out_size) {
    const float* x    = (const float*)d_in[0];
    const float* Z0   = (const float*)d_in[1];
    const float* Wrec = (const float*)d_in[2];
    const float* brec = (const float*)d_in[3];
    const float* Wsyn = (const float*)d_in[4];
    const float* bsyn = (const float*)d_in[5];
    const float* Wout = (const float*)d_in[6];
    const float* bout = (const float*)d_in[7];
    const void*  aidx = d_in[8];
    float* out = (float*)d_out;

    static bool attr_set = false;
    if (!attr_set) {
        cudaFuncSetAttribute(k_main, cudaFuncAttributeMaxDynamicSharedMemorySize, g::SM_TOTAL);
        attr_set = true;
    }

    k_decode<<<1, 1024>>>(aidx);
    k_gate<<<g::A, 256>>>(Z0);
    k_build<<<dim3(g::N / 256, g::B), 256>>>(Z0, x);
    k_main<<<dim3(g::N / g::MT, g::KSPLIT), 256, g::SM_TOTAL>>>(Wsyn, Wrec);
    k_final<<<((size_t)g::N * g::B) / 256, 256>>>(bsyn, brec);
    k_out<<<dim3(g::OUTD, g::B), 256>>>(Wout, bout, out);
}

// round 5
// speedup vs baseline: 3.8502x; 1.2289x over previous
#include <cuda_runtime.h>
#include <cuda_bf16.h>
#include <cstdint>
#include <cstddef>
#include <math.h>

namespace g {
constexpr int B = 32, A = 4, NPER = 2048, N = 8192, DIN = 1024, OUTD = 11;
constexpr int KTOT   = N + DIN;              // 9216
constexpr int KSPLIT = 6;
constexpr int KPART  = KTOT / KSPLIT;        // 1536
constexpr int KC     = 32;                   // k per chunk
constexpr int MT     = 128;                  // rows per CTA
constexpr int NCH    = KPART / KC;           // 48
constexpr int STAGES = 3;
constexpr float THRESH = 0.05f;
constexpr float GTOT  = (float)(B * NPER);   // 65536

// smem strides (floats) chosen for conflict-free mma fragment loads
constexpr int ASTR = 36;
constexpr int BSTR = 40;
constexpr int SA_F = MT * ASTR;              // 4608 floats (18432 B)
constexpr int SB_F = KC * BSTR;              // 1280 floats (5120 B)
constexpr int STAGE_F = SA_F + SB_F;         // 5888 floats (23552 B)
constexpr int STAGE_BYTES = STAGE_F * 4;
constexpr int SM_TOTAL = STAGES * STAGE_BYTES;  // 70656 B -> 3 CTAs/SM
}

// ------------------ device scratch ------------------
__device__ float g_gsum[g::A];
__device__ int   g_perm[g::N];                              // perm order -> natural col
__device__ float g_Ueff[(size_t)g::A * g::N * g::B];        // [o][c][b], 4 MB
__device__ float g_Xt[(size_t)g::DIN * g::B];               // [k][b]
__device__ float g_part[(size_t)g::KSPLIT * g::N * g::B];   // [kh][b][j], 6 MB
__device__ float g_Zp[(size_t)g::B * g::N];                 // Z in perm order [b][j]

// ------------------ helpers ------------------
__device__ __forceinline__ uint32_t smem_u32(const void* p) {
    uint32_t a;
    asm("{ .reg .u64 t; cvta.to.shared.u64 t, %1; cvt.u32.u64 %0, t; }" : "=r"(a) : "l"(p));
    return a;
}
__device__ __forceinline__ void cp16(uint32_t dst, const void* src) {
    asm volatile("cp.async.cg.shared.global [%0], [%1], 16;" :: "r"(dst), "l"(src) : "memory");
}
#define CP_COMMIT() asm volatile("cp.async.commit_group;" ::: "memory")
#define CP_WAIT1()  asm volatile("cp.async.wait_group 1;" ::: "memory")

__device__ __forceinline__ float rna_tf32(float v) {
    float r;
    asm("cvt.rna.tf32.f32 %0, %1;" : "=f"(r) : "f"(v));
    return r;
}
__device__ __forceinline__ uint32_t cvt_tf32_bits(float v) {
    uint32_t r;
    asm("cvt.rna.tf32.f32 %0, %1;" : "=r"(r) : "f"(v));
    return r;
}
__device__ __forceinline__ void mma_tf32(float& d0, float& d1, float& d2, float& d3,
                                         uint32_t a0, uint32_t a1, uint32_t a2, uint32_t a3,
                                         uint32_t b0, uint32_t b1) {
    asm volatile(
        "mma.sync.aligned.m16n8k8.row.col.f32.tf32.tf32.f32 "
        "{%0,%1,%2,%3}, {%4,%5,%6,%7}, {%8,%9}, {%0,%1,%2,%3};"
        : "+f"(d0), "+f"(d1), "+f"(d2), "+f"(d3)
        : "r"(a0), "r"(a1), "r"(a2), "r"(a3), "r"(b0), "r"(b1));
}

// =========================================================================
// 1) decode area_idx (int32 or int64) -> g_perm; zero gate sums
// =========================================================================
__global__ void k_decode(const void* area_idx_raw) {
    const unsigned* w32 = (const unsigned*)area_idx_raw;
    int t = threadIdx.x;  // 1024
    if (t < g::A) g_gsum[t] = 0.f;
    unsigned acc = 0;
    for (int i = t; i < g::N; i += 1024) acc |= w32[2 * i + 1];
    for (int o = 16; o; o >>= 1) acc |= __shfl_xor_sync(0xFFFFFFFFu, acc, o);
    __shared__ unsigned red[32];
    __shared__ int is64_s;
    if ((t & 31) == 0) red[t >> 5] = acc;
    __syncthreads();
    if (t < 32) {
        unsigned v = red[t];
        for (int o = 16; o; o >>= 1) v |= __shfl_xor_sync(0xFFFFFFFFu, v, o);
        if (t == 0) is64_s = (v == 0u) ? 1 : 0;
    }
    __syncthreads();
    bool is64 = (is64_s != 0);
    const long long* p64 = (const long long*)area_idx_raw;
    const int*       p32 = (const int*)area_idx_raw;
    for (int i = t; i < g::N; i += 1024)
        g_perm[i] = is64 ? (int)p64[i] : p32[i];
}

// =========================================================================
// 2) gate partial sums: 64 CTAs, atomicAdd into g_gsum[a]
// =========================================================================
__global__ void k_gate(const float* __restrict__ Z0) {
    int a  = blockIdx.x >> 4;          // 4 areas x 16 slices
    int sl = blockIdx.x & 15;
    int t  = threadIdx.x;              // 256
    int b  = t >> 3;                   // 0..31
    int m0 = sl * 128 + (t & 7) * 16;
    const float* src = Z0 + ((size_t)b * g::A + a) * g::NPER + m0;
    float s = 0.f;
#pragma unroll
    for (int i = 0; i < 16; i++) s += fabsf(src[i]);
    for (int o = 16; o; o >>= 1) s += __shfl_xor_sync(0xFFFFFFFFu, s, o);
    __shared__ float red[8];
    if ((t & 31) == 0) red[t >> 5] = s;
    __syncthreads();
    if (t == 0) {
        float tot = 0.f;
#pragma unroll
        for (int i = 0; i < 8; i++) tot += red[i];
        atomicAdd(&g_gsum[a], tot);
    }
}

// =========================================================================
// 3) Ueff[o][c][b] = rna(scale*gate*Z0), coalesced over b; Xt[k][b] = rna(x)
// =========================================================================
__global__ void k_build(const float* __restrict__ Z0, const float* __restrict__ x) {
    int tid = threadIdx.x;                  // 256 = 8 j x 32 b
    int j = blockIdx.x * 8 + (tid >> 5);    // perm position, 1024 blocks
    int b = tid & 31;
    int c = g_perm[j];
    int a = j >> 11;
    float gate = (g_gsum[a] > g::THRESH * g::GTOT) ? 1.f : 0.f;
    float zg = Z0[((size_t)b * g::A + a) * g::NPER + (j & (g::NPER - 1))] * gate;
#pragma unroll
    for (int o = 0; o < g::A; o++) {
        float sc = (o == a) ? 0.8f : 0.1f;
        g_Ueff[(((size_t)o * g::N + c) << 5) + b] = rna_tf32(sc * zg);
    }
    if (j < g::DIN) g_Xt[((size_t)j << 5) + b] = rna_tf32(x[(size_t)b * g::DIN + j]);
}

// =========================================================================
// 4) main GEMM via mma.sync tf32. grid (64, 6), 256 threads (8 warps).
// =========================================================================
__global__ void __launch_bounds__(256) k_main(const float* __restrict__ Wsyn,
                                              const float* __restrict__ Wrec) {
    extern __shared__ float smem[];
    __shared__ int srow[g::MT];
    const uint32_t su = smem_u32(smem);

    const int tid = threadIdx.x, wid = tid >> 5, lane = tid & 31;
    const int gq = lane >> 2, tq = lane & 3;
    const int j0 = blockIdx.x * g::MT;
    const int o  = j0 >> 11;
    const int kh = blockIdx.y;
    const int kbase = kh * g::KPART;
    const int nsyn = min(g::NCH, (g::N - kbase) / g::KC);  // chunks from Wsyn

    if (tid < g::MT) srow[tid] = g_perm[j0 + tid];
    __syncthreads();

    // hoisted per-thread pointers (advance +128B/chunk for A, +4KB/chunk for B)
    const char* asyn[4];
    const char* arec[4];
    uint32_t dstA[4];
#pragma unroll
    for (int i = 0; i < 4; i++) {
        int ga = tid + i * 256;
        int row = ga >> 3, kg = ga & 7;
        asyn[i] = (const char*)(Wsyn + (size_t)srow[row] * g::N + kbase + kg * 4);
        arec[i] = (const char*)(Wrec + (size_t)srow[row] * g::DIN + kg * 4);
        dstA[i] = su + row * (g::ASTR * 4) + kg * 16;
    }
    const int krow = tid >> 3, ng = tid & 7;
    const char* bsyn = (const char*)(g_Ueff + (((size_t)o * g::N + kbase + krow) << 5) + ng * 4);
    const char* brec = (const char*)(g_Xt + ((size_t)krow << 5) + ng * 4);
    const uint32_t dstB = su + g::SA_F * 4 + krow * (g::BSTR * 4) + ng * 16;

    auto issue = [&](int q) {
        const uint32_t so = (uint32_t)(q % g::STAGES) * g::STAGE_BYTES;
        if (q < nsyn) {
            const size_t offA = (size_t)q * 128;
#pragma unroll
            for (int i = 0; i < 4; i++) cp16(dstA[i] + so, asyn[i] + offA);
            cp16(dstB + so, bsyn + (size_t)q * 4096);
        } else {
            const int qr = q - nsyn;
            const size_t offA = (size_t)qr * 128;
#pragma unroll
            for (int i = 0; i < 4; i++) cp16(dstA[i] + so, arec[i] + offA);
            cp16(dstB + so, brec + (size_t)qr * 4096);
        }
    };

    float acc[4][4];
#pragma unroll
    for (int i = 0; i < 4; i++)
#pragma unroll
        for (int jn = 0; jn < 4; jn++) acc[i][jn] = 0.f;

    for (int q = 0; q < g::STAGES - 1; q++) { issue(q); CP_COMMIT(); }

    const int arow = wid * 16 + gq;

    for (int q = 0; q < g::NCH; q++) {
        CP_WAIT1();
        __syncthreads();
        if (q + g::STAGES - 1 < g::NCH) issue(q + g::STAGES - 1);
        CP_COMMIT();

        const float* As = smem + (q % g::STAGES) * g::STAGE_F;
        const float* Bs = As + g::SA_F;
#pragma unroll
        for (int ks = 0; ks < 4; ks++) {
            const int kk = ks * 8;
            uint32_t a0 = cvt_tf32_bits(As[arow * g::ASTR + kk + tq]);
            uint32_t a1 = cvt_tf32_bits(As[(arow + 8) * g::ASTR + kk + tq]);
            uint32_t a2 = cvt_tf32_bits(As[arow * g::ASTR + kk + tq + 4]);
            uint32_t a3 = cvt_tf32_bits(As[(arow + 8) * g::ASTR + kk + tq + 4]);
#pragma unroll
            for (int nt = 0; nt < 4; nt++) {
                uint32_t b0 = __float_as_uint(Bs[(kk + tq) * g::BSTR + nt * 8 + gq]);
                uint32_t b1 = __float_as_uint(Bs[(kk + tq + 4) * g::BSTR + nt * 8 + gq]);
                mma_tf32(acc[nt][0], acc[nt][1], acc[nt][2], acc[nt][3],
                         a0, a1, a2, a3, b0, b1);
            }
        }
    }

    // epilogue: part[kh][b][j]
    float* dst = g_part + (size_t)kh * ((size_t)g::N * g::B);
    const int jr = j0 + wid * 16 + gq;
#pragma unroll
    for (int nt = 0; nt < 4; nt++) {
        int bc = nt * 8 + 2 * tq;
        dst[(size_t)bc * g::N + jr]           = acc[nt][0];
        dst[(size_t)(bc + 1) * g::N + jr]     = acc[nt][1];
        dst[(size_t)bc * g::N + jr + 8]       = acc[nt][2];
        dst[(size_t)(bc + 1) * g::N + jr + 8] = acc[nt][3];
    }
}

// =========================================================================
// 5) combine partials + bias + tanh -> Zp[b][j] (perm order, coalesced)
// =========================================================================
__global__ void k_final(const float* __restrict__ bsyn, const float* __restrict__ brec) {
    size_t idx = (size_t)blockIdx.x * 256 + threadIdx.x;   // b*N + j
    int j = (int)(idx & (g::N - 1));
    int rp = g_perm[j];
    int o = j >> 11;
    float gate = (g_gsum[o] > g::THRESH * g::GTOT) ? 1.f : 0.f;
    constexpr size_t S = (size_t)g::N * g::B;
    float v = g_part[idx];
#pragma unroll
    for (int kh = 1; kh < g::KSPLIT; kh++) v += g_part[idx + kh * S];
    v += gate * bsyn[rp] + brec[rp];
    g_Zp[idx] = tanhf(v);
}

// =========================================================================
// 6) output lobe: gathers Wout by perm, Z read coalesced in perm order
// =========================================================================
__global__ void k_out(const float* __restrict__ Wout, const float* __restrict__ bout,
                      float* __restrict__ out) {
    int tt = blockIdx.x, b = blockIdx.y, t = threadIdx.x;
    const float* wrow = Wout + (size_t)tt * g::N;
    const float* zrow = g_Zp + (size_t)b * g::N;
    float s = 0.f;
    for (int q = t; q < g::N; q += 256) s += wrow[g_perm[q]] * zrow[q];
    for (int o = 16; o; o >>= 1) s += __shfl_xor_sync(0xFFFFFFFFu, s, o);
    __shared__ float red[8];
    if ((t & 31) == 0) red[t >> 5] = s;
    __syncthreads();
    if (t == 0) {
        float tot = 0.f;
#pragma unroll
        for (int i = 0; i < 8; i++) tot += red[i];
        tot += bout[tt];
        if (tt < 10) out[(size_t)b * 10 + tt] = tot;
        else         out[320 + b] = 1.f / (1.f + expf(-tot));
    }
}

// =========================================================================
extern "C" void kernel_launch(void* const* d_in, const int* in_sizes, int n_in,
                              void* d_out, int out_size) {
    const float* x    = (const float*)d_in[0];
    const float* Z0   = (const float*)d_in[1];
    const float* Wrec = (const float*)d_in[2];
    const float* brec = (const float*)d_in[3];
    const float* Wsyn = (const float*)d_in[4];
    const float* bsyn = (const float*)d_in[5];
    const float* Wout = (const float*)d_in[6];
    const float* bout = (const float*)d_in[7];
    const void*  aidx = d_in[8];
    float* out = (float*)d_out;

    static bool attr_set = false;
    if (!attr_set) {
        cudaFuncSetAttribute(k_main, cudaFuncAttributeMaxDynamicSharedMemorySize, g::SM_TOTAL);
        attr_set = true;
    }

    k_decode<<<1, 1024>>>(aidx);
    k_gate<<<64, 256>>>(Z0);
    k_build<<<g::N / 8, 256>>>(Z0, x);
    k_main<<<dim3(g::N / g::MT, g::KSPLIT), 256, g::SM_TOTAL>>>(Wsyn, Wrec);
    k_final<<<((size_t)g::N * g::B) / 256, 256>>>(bsyn, brec);
    k_out<<<dim3(g::OUTD, g::B), 256>>>(Wout, bout, out);
}

// round 6
// speedup vs baseline: 4.3254x; 1.1234x over previous
#include <cuda_runtime.h>
#include <cuda_bf16.h>
#include <cstdint>
#include <cstddef>
#include <math.h>

namespace g {
constexpr int B = 32, A = 4, NPER = 2048, N = 8192, DIN = 1024, OUTD = 11;
constexpr int KTOT   = N + DIN;              // 9216
constexpr int KSPLIT = 9;                    // kh 0..7 = Wsyn, kh 8 = Wrec
constexpr int KPART  = 1024;
constexpr int KC     = 32;
constexpr int MT     = 256;                  // rows per CTA (8 warps x 32 rows)
constexpr int NCH    = KPART / KC;           // 32
constexpr int STAGES = 3;
constexpr float THRESH = 0.05f;
constexpr float GTOT  = (float)(B * NPER);

constexpr int A_FLOATS = MT * 32;            // 8192 floats (32 KB), xor-swizzled
constexpr int BSTR = 40;                     // B row stride floats
constexpr int B_FLOATS = KC * BSTR;          // 1280 floats (5 KB)
constexpr int STAGE_F = A_FLOATS + B_FLOATS; // 9472
constexpr int STAGE_BYTES = STAGE_F * 4;     // 37888
constexpr int SM_TOTAL = STAGES * STAGE_BYTES;  // 113664 -> 2 CTAs/SM
}

// ------------------ device scratch ------------------
__device__ float g_gsum[g::A];
__device__ int   g_perm[g::N];
__device__ float g_Ueff[(size_t)g::A * g::N * g::B];        // [o][c][b], 4 MB
__device__ float g_Xt[(size_t)g::DIN * g::B];               // [k][b]
__device__ float g_part[(size_t)g::KSPLIT * g::N * g::B];   // [kh][b][j], 9 MB
__device__ float g_Zp[(size_t)g::B * g::N];                 // Z perm order [b][j]

// ------------------ helpers ------------------
__device__ __forceinline__ uint32_t smem_u32(const void* p) {
    uint32_t a;
    asm("{ .reg .u64 t; cvta.to.shared.u64 t, %1; cvt.u32.u64 %0, t; }" : "=r"(a) : "l"(p));
    return a;
}
__device__ __forceinline__ void cp16(uint32_t dst, const void* src) {
    asm volatile("cp.async.cg.shared.global [%0], [%1], 16;" :: "r"(dst), "l"(src) : "memory");
}
#define CP_COMMIT() asm volatile("cp.async.commit_group;" ::: "memory")
#define CP_WAIT1()  asm volatile("cp.async.wait_group 1;" ::: "memory")

__device__ __forceinline__ float rna_tf32(float v) {
    float r;
    asm("cvt.rna.tf32.f32 %0, %1;" : "=f"(r) : "f"(v));
    return r;
}
__device__ __forceinline__ uint32_t cvt_tf32_bits(float v) {
    uint32_t r;
    asm("cvt.rna.tf32.f32 %0, %1;" : "=r"(r) : "f"(v));
    return r;
}
__device__ __forceinline__ void mma_tf32(float& d0, float& d1, float& d2, float& d3,
                                         uint32_t a0, uint32_t a1, uint32_t a2, uint32_t a3,
                                         uint32_t b0, uint32_t b1) {
    asm volatile(
        "mma.sync.aligned.m16n8k8.row.col.f32.tf32.tf32.f32 "
        "{%0,%1,%2,%3}, {%4,%5,%6,%7}, {%8,%9}, {%0,%1,%2,%3};"
        : "+f"(d0), "+f"(d1), "+f"(d2), "+f"(d3)
        : "r"(a0), "r"(a1), "r"(a2), "r"(a3), "r"(b0), "r"(b1));
}

// =========================================================================
// 1) decode area_idx (int32 or int64) -> g_perm; zero gate sums
// =========================================================================
__global__ void k_decode(const void* area_idx_raw) {
    const unsigned* w32 = (const unsigned*)area_idx_raw;
    int t = threadIdx.x;  // 1024
    if (t < g::A) g_gsum[t] = 0.f;
    unsigned acc = 0;
    for (int i = t; i < g::N; i += 1024) acc |= w32[2 * i + 1];
    for (int o = 16; o; o >>= 1) acc |= __shfl_xor_sync(0xFFFFFFFFu, acc, o);
    __shared__ unsigned red[32];
    __shared__ int is64_s;
    if ((t & 31) == 0) red[t >> 5] = acc;
    __syncthreads();
    if (t < 32) {
        unsigned v = red[t];
        for (int o = 16; o; o >>= 1) v |= __shfl_xor_sync(0xFFFFFFFFu, v, o);
        if (t == 0) is64_s = (v == 0u) ? 1 : 0;
    }
    __syncthreads();
    bool is64 = (is64_s != 0);
    const long long* p64 = (const long long*)area_idx_raw;
    const int*       p32 = (const int*)area_idx_raw;
    for (int i = t; i < g::N; i += 1024)
        g_perm[i] = is64 ? (int)p64[i] : p32[i];
}

// =========================================================================
// 2) gate partial sums
// =========================================================================
__global__ void k_gate(const float* __restrict__ Z0) {
    int a  = blockIdx.x >> 4;
    int sl = blockIdx.x & 15;
    int t  = threadIdx.x;
    int b  = t >> 3;
    int m0 = sl * 128 + (t & 7) * 16;
    const float* src = Z0 + ((size_t)b * g::A + a) * g::NPER + m0;
    float s = 0.f;
#pragma unroll
    for (int i = 0; i < 16; i++) s += fabsf(src[i]);
    for (int o = 16; o; o >>= 1) s += __shfl_xor_sync(0xFFFFFFFFu, s, o);
    __shared__ float red[8];
    if ((t & 31) == 0) red[t >> 5] = s;
    __syncthreads();
    if (t == 0) {
        float tot = 0.f;
#pragma unroll
        for (int i = 0; i < 8; i++) tot += red[i];
        atomicAdd(&g_gsum[a], tot);
    }
}

// =========================================================================
// 3) build Ueff / Xt with coalesced loads via smem transpose.
//    blocks 0..255: 32 j-positions each (same area); blocks 256..287: x.
// =========================================================================
__global__ void k_build(const float* __restrict__ Z0, const float* __restrict__ x) {
    __shared__ float sm[32][33];
    int t = threadIdx.x, w = t >> 5, l = t & 31;
    int blk = blockIdx.x;
    if (blk < 256) {
        int j0 = blk * 32;
        int a  = j0 >> 11;
        int m0 = j0 & (g::NPER - 1);
        // phase 1: coalesced load Z0[b][a][m0..m0+31]
#pragma unroll
        for (int bi = 0; bi < 4; bi++) {
            int b = w + 8 * bi;
            sm[b][l] = Z0[((size_t)b * g::A + a) * g::NPER + m0 + l];
        }
        __syncthreads();
        float gate = (g_gsum[a] > g::THRESH * g::GTOT) ? 1.f : 0.f;
        // phase 2: coalesced stores over b
#pragma unroll
        for (int ji = 0; ji < 4; ji++) {
            int jloc = w + 8 * ji;
            int c = g_perm[j0 + jloc];
            float zg = sm[l][jloc] * gate;
#pragma unroll
            for (int o = 0; o < g::A; o++) {
                float sc = (o == a) ? 0.8f : 0.1f;
                g_Ueff[(((size_t)o * g::N + c) << 5) + l] = rna_tf32(sc * zg);
            }
        }
    } else {
        int k0 = (blk - 256) * 32;
#pragma unroll
        for (int bi = 0; bi < 4; bi++) {
            int b = w + 8 * bi;
            sm[b][l] = x[(size_t)b * g::DIN + k0 + l];
        }
        __syncthreads();
#pragma unroll
        for (int ji = 0; ji < 4; ji++) {
            int kloc = w + 8 * ji;
            g_Xt[((size_t)(k0 + kloc) << 5) + l] = rna_tf32(sm[l][kloc]);
        }
    }
}

// =========================================================================
// 4) main GEMM via mma.sync tf32. grid (32, 9), 256 threads, 2 CTAs/SM.
//    Warp tile 32 rows x 32 b. A xor-swizzled (stride 32), B stride 40.
// =========================================================================
__global__ void __launch_bounds__(256) k_main(const float* __restrict__ Wsyn,
                                              const float* __restrict__ Wrec) {
    extern __shared__ float smem[];
    __shared__ int srow[g::MT];
    const uint32_t su = smem_u32(smem);

    const int tid = threadIdx.x, wid = tid >> 5, lane = tid & 31;
    const int gq = lane >> 2, tq = lane & 3;
    const int j0 = blockIdx.x * g::MT;
    const int kh = blockIdx.y;
    const bool rec = (kh == 8);
    const int kbase = rec ? 0 : kh * g::KPART;
    const char* wb = (const char*)(rec ? Wrec : Wsyn);
    const uint32_t ldb = rec ? (g::DIN * 4) : (g::N * 4);

    srow[tid] = g_perm[j0 + tid];
    __syncthreads();

    // A cp.async: thread -> (kg, rowb), rows rowb + 32*i
    const int kg = tid & 7, rowb = tid >> 3;
    uint32_t aoff[8];
#pragma unroll
    for (int i = 0; i < 8; i++) aoff[i] = (uint32_t)srow[rowb + 32 * i] * ldb;
    const uint32_t dstAbase = su + rowb * 128 + ((kg ^ (rowb & 7)) * 16);
    const uint32_t colbyte = (uint32_t)kbase * 4 + kg * 16;
    // B cp.async
    const int krow = tid >> 3, ng = tid & 7;
    const char* bsrc = (const char*)(rec
        ? g_Xt + ((size_t)krow << 5) + ng * 4
        : g_Ueff + (((size_t)(blockIdx.x >> 3) * g::N + kbase + krow) << 5) + ng * 4);
    const uint32_t dstB = su + g::A_FLOATS * 4 + krow * (g::BSTR * 4) + ng * 16;

    auto issue = [&](int q) {
        const uint32_t so = (uint32_t)(q % g::STAGES) * g::STAGE_BYTES;
        const uint32_t cb = colbyte + (uint32_t)q * 128;
#pragma unroll
        for (int i = 0; i < 8; i++)
            cp16(dstAbase + so + i * 4096, wb + (size_t)aoff[i] + cb);
        cp16(dstB + so, bsrc + (size_t)q * 4096);
    };

    float acc[2][4][4];
#pragma unroll
    for (int mt = 0; mt < 2; mt++)
#pragma unroll
        for (int nt = 0; nt < 4; nt++)
#pragma unroll
            for (int c = 0; c < 4; c++) acc[mt][nt][c] = 0.f;

    for (int q = 0; q < g::STAGES - 1; q++) { issue(q); CP_COMMIT(); }

    const int xo = 4 * gq;

    for (int q = 0; q < g::NCH; q++) {
        CP_WAIT1();
        __syncthreads();
        if (q + g::STAGES - 1 < g::NCH) issue(q + g::STAGES - 1);
        CP_COMMIT();

        const float* As = smem + (q % g::STAGES) * g::STAGE_F;
        const float* Bs = As + g::A_FLOATS;
#pragma unroll
        for (int ks = 0; ks < 4; ks++) {
            const int kc = ks * 8 + tq;
            uint32_t b0[4], b1[4];
#pragma unroll
            for (int nt = 0; nt < 4; nt++) {
                b0[nt] = __float_as_uint(Bs[kc * g::BSTR + nt * 8 + gq]);
                b1[nt] = __float_as_uint(Bs[(kc + 4) * g::BSTR + nt * 8 + gq]);
            }
#pragma unroll
            for (int mt = 0; mt < 2; mt++) {
                const int r = wid * 32 + mt * 16 + gq;
                uint32_t a0 = cvt_tf32_bits(As[r * 32 + (kc ^ xo)]);
                uint32_t a1 = cvt_tf32_bits(As[(r + 8) * 32 + (kc ^ xo)]);
                uint32_t a2 = cvt_tf32_bits(As[r * 32 + ((kc + 4) ^ xo)]);
                uint32_t a3 = cvt_tf32_bits(As[(r + 8) * 32 + ((kc + 4) ^ xo)]);
#pragma unroll
                for (int nt = 0; nt < 4; nt++)
                    mma_tf32(acc[mt][nt][0], acc[mt][nt][1], acc[mt][nt][2], acc[mt][nt][3],
                             a0, a1, a2, a3, b0[nt], b1[nt]);
            }
        }
    }

    // epilogue: part[kh][b][j]
    float* dst = g_part + (size_t)kh * ((size_t)g::N * g::B);
#pragma unroll
    for (int mt = 0; mt < 2; mt++) {
        const int jr = j0 + wid * 32 + mt * 16 + gq;
#pragma unroll
        for (int nt = 0; nt < 4; nt++) {
            int bc = nt * 8 + 2 * tq;
            dst[(size_t)bc * g::N + jr]           = acc[mt][nt][0];
            dst[(size_t)(bc + 1) * g::N + jr]     = acc[mt][nt][1];
            dst[(size_t)bc * g::N + jr + 8]       = acc[mt][nt][2];
            dst[(size_t)(bc + 1) * g::N + jr + 8] = acc[mt][nt][3];
        }
    }
}

// =========================================================================
// 5) combine partials + bias + tanh -> Zp[b][j]
// =========================================================================
__global__ void k_final(const float* __restrict__ bsyn, const float* __restrict__ brec) {
    size_t idx = (size_t)blockIdx.x * 256 + threadIdx.x;   // b*N + j
    int j = (int)(idx & (g::N - 1));
    int rp = g_perm[j];
    int o = j >> 11;
    float gate = (g_gsum[o] > g::THRESH * g::GTOT) ? 1.f : 0.f;
    constexpr size_t S = (size_t)g::N * g::B;
    float v = g_part[idx];
#pragma unroll
    for (int kh = 1; kh < g::KSPLIT; kh++) v += g_part[idx + kh * S];
    v += gate * bsyn[rp] + brec[rp];
    g_Zp[idx] = tanhf(v);
}

// =========================================================================
// 6) output lobe
// =========================================================================
__global__ void k_out(const float* __restrict__ Wout, const float* __restrict__ bout,
                      float* __restrict__ out) {
    int tt = blockIdx.x, b = blockIdx.y, t = threadIdx.x;
    const float* wrow = Wout + (size_t)tt * g::N;
    const float* zrow = g_Zp + (size_t)b * g::N;
    float s = 0.f;
    for (int q = t; q < g::N; q += 256) s += wrow[g_perm[q]] * zrow[q];
    for (int o = 16; o; o >>= 1) s += __shfl_xor_sync(0xFFFFFFFFu, s, o);
    __shared__ float red[8];
    if ((t & 31) == 0) red[t >> 5] = s;
    __syncthreads();
    if (t == 0) {
        float tot = 0.f;
#pragma unroll
        for (int i = 0; i < 8; i++) tot += red[i];
        tot += bout[tt];
        if (tt < 10) out[(size_t)b * 10 + tt] = tot;
        else         out[320 + b] = 1.f / (1.f + expf(-tot));
    }
}

// =========================================================================
extern "C" void kernel_launch(void* const* d_in, const int* in_sizes, int n_in,
                              void* d_out, int out_size) {
    const float* x    = (const float*)d_in[0];
    const float* Z0   = (const float*)d_in[1];
    const float* Wrec = (const float*)d_in[2];
    const float* brec = (const float*)d_in[3];
    const float* Wsyn = (const float*)d_in[4];
    const float* bsyn = (const float*)d_in[5];
    const float* Wout = (const float*)d_in[6];
    const float* bout = (const float*)d_in[7];
    const void*  aidx = d_in[8];
    float* out = (float*)d_out;

    static bool attr_set = false;
    if (!attr_set) {
        cudaFuncSetAttribute(k_main, cudaFuncAttributeMaxDynamicSharedMemorySize, g::SM_TOTAL);
        attr_set = true;
    }

    k_decode<<<1, 1024>>>(aidx);
    k_gate<<<64, 256>>>(Z0);
    k_build<<<288, 256>>>(Z0, x);
    k_main<<<dim3(g::N / g::MT, g::KSPLIT), 256, g::SM_TOTAL>>>(Wsyn, Wrec);
    k_final<<<((size_t)g::N * g::B) / 256, 256>>>(bsyn, brec);
    k_out<<<dim3(g::OUTD, g::B), 256>>>(Wout, bout, out);
}